// round 14
// baseline (speedup 1.0000x reference)
#include <cuda_runtime.h>

#define NTHREADS 512
#define ROWS_PER_CTA 64
#define NCTA 128          // 8192 / 64
#define OUTSTR 771        // 257*3

// 512 threads = 8 independent groups of 64 (8 rows each).
// Group q = warps {2q, 2q+1}: u = tid & 63 (hidden unit), q = tid >> 6.
// Thread owns 8 rows (4 float2 pairs). Warp = 32 consecutive u, same q.
// Groups sync only via named barriers (64 threads); each SMSP hosts 4 warps
// from 4 different groups -> 4 independent streams per scheduler.
struct SMem {
    float4 wpack[76][64];   // {Wi,Wf,Wg,Wo}[.,k] for unit u        (77824 B)
    float4 xbuf[2][76*21];  // [phase][k*21 + set*10 + q], set=0,1  (51072 B)
    float  w1t[64][64];     // w1t[k][u] = W1[u][k]                 (16384 B)
    float2 zhalf[8][2][4];  // [q][warp-half][pair]                 (  512 B)
};

__device__ __forceinline__ void bar_grp(int grp) {
    asm volatile("bar.sync %0, 64;" :: "r"(grp + 1) : "memory");
}

__device__ __forceinline__ float tanha(float x) {
    float r;
    asm("tanh.approx.f32 %0, %1;" : "=f"(r) : "f"(x));
    return r;
}
__device__ __forceinline__ float siga(float x) {
    return fmaf(0.5f, tanha(0.5f * x), 0.5f);
}

// 4 accumulators += pair-vector * scalar, via packed fma.rn.f32x2
__device__ __forceinline__ void gate4(float sw,
                                      float2 p0, float2 p1, float2 p2, float2 p3,
                                      float2& a0, float2& a1, float2& a2, float2& a3) {
    asm("{\n\t"
        ".reg .b64 rb, rx, ra;\n\t"
        "mov.b64 rb, {%8,%8};\n\t"
        "mov.b64 rx, {%9,%10};  mov.b64 ra, {%0,%1}; fma.rn.f32x2 ra, rx, rb, ra; mov.b64 {%0,%1}, ra;\n\t"
        "mov.b64 rx, {%11,%12}; mov.b64 ra, {%2,%3}; fma.rn.f32x2 ra, rx, rb, ra; mov.b64 {%2,%3}, ra;\n\t"
        "mov.b64 rx, {%13,%14}; mov.b64 ra, {%4,%5}; fma.rn.f32x2 ra, rx, rb, ra; mov.b64 {%4,%5}, ra;\n\t"
        "mov.b64 rx, {%15,%16}; mov.b64 ra, {%6,%7}; fma.rn.f32x2 ra, rx, rb, ra; mov.b64 {%6,%7}, ra;\n\t"
        "}"
        : "+f"(a0.x), "+f"(a0.y), "+f"(a1.x), "+f"(a1.y),
          "+f"(a2.x), "+f"(a2.y), "+f"(a3.x), "+f"(a3.y)
        : "f"(sw),
          "f"(p0.x), "f"(p0.y), "f"(p1.x), "f"(p1.y),
          "f"(p2.x), "f"(p2.y), "f"(p3.x), "f"(p3.y));
}

// LSTM cell, 4 pairs. XREG: k=2 (x2) / k=3 (x3) from registers (gen phase).
template<bool XREG>
__device__ __forceinline__ void lstm_step4(const SMem* s, int u, int q, int ph,
                                           const float2 x2[4], const float2 x3[4],
                                           float bi, float bf, float bg, float bo,
                                           float2 c4[4], float2 h4[4]) {
    float2 ai[4], af4[4], ag[4], ao[4];
#pragma unroll
    for (int p = 0; p < 4; ++p) {
        ai[p] = make_float2(bi, bi);
        af4[p] = make_float2(bf, bf);
        ag[p] = make_float2(bg, bg);
        ao[p] = make_float2(bo, bo);
    }
    const float4* wp = &s->wpack[0][u];       // stride 64 float4 per k
    const float4* xp = &s->xbuf[ph][q];       // +k*21, sets at +0,+10

    auto doK = [&](float4 w, float4 X0, float4 X1) {
        float2 p0 = make_float2(X0.x, X0.y), p1 = make_float2(X0.z, X0.w);
        float2 p2 = make_float2(X1.x, X1.y), p3 = make_float2(X1.z, X1.w);
        gate4(w.x, p0, p1, p2, p3, ai[0], ai[1], ai[2], ai[3]);
        gate4(w.y, p0, p1, p2, p3, af4[0], af4[1], af4[2], af4[3]);
        gate4(w.z, p0, p1, p2, p3, ag[0], ag[1], ag[2], ag[3]);
        gate4(w.w, p0, p1, p2, p3, ao[0], ao[1], ao[2], ao[3]);
    };
    auto doKreg = [&](float4 w, const float2 x[4]) {
        gate4(w.x, x[0], x[1], x[2], x[3], ai[0], ai[1], ai[2], ai[3]);
        gate4(w.y, x[0], x[1], x[2], x[3], af4[0], af4[1], af4[2], af4[3]);
        gate4(w.z, x[0], x[1], x[2], x[3], ag[0], ag[1], ag[2], ag[3]);
        gate4(w.w, x[0], x[1], x[2], x[3], ao[0], ao[1], ao[2], ao[3]);
    };

    doK(wp[0], xp[0], xp[10]);                                      // k=0
    doK(wp[64], xp[21], xp[31]);                                    // k=1
    if (XREG) {
        doKreg(wp[2 * 64], x2);                                     // k=2 (dp)
        doKreg(wp[3 * 64], x3);                                     // k=3 (dist)
    } else {
        doK(wp[2 * 64], xp[42], xp[52]);
        doK(wp[3 * 64], xp[63], xp[73]);
    }
    // pipelined k = 4..75
    float4 wc = wp[4 * 64];
    float4 a0 = xp[4 * 21], a1 = xp[4 * 21 + 10];
#pragma unroll 4
    for (int k = 4; k < 75; ++k) {
        float4 wn = wp[(k + 1) * 64];
        float4 n0 = xp[(k + 1) * 21], n1 = xp[(k + 1) * 21 + 10];
        doK(wc, a0, a1);
        wc = wn; a0 = n0; a1 = n1;
    }
    doK(wc, a0, a1);                                                // k=75

#pragma unroll
    for (int p = 0; p < 4; ++p) {
        float ix = siga(ai[p].x), fx = siga(af4[p].x), gx = tanha(ag[p].x), ox = siga(ao[p].x);
        c4[p].x = fmaf(fx, c4[p].x, ix * gx);
        h4[p].x = ox * tanha(c4[p].x);
        float iy = siga(ai[p].y), fy = siga(af4[p].y), gy = tanha(ag[p].y), oy = siga(ao[p].y);
        c4[p].y = fmaf(fy, c4[p].y, iy * gy);
        h4[p].y = oy * tanha(c4[p].y);
    }
}

__global__ void __launch_bounds__(NTHREADS, 1)
lstm_fused(const float* __restrict__ noise, const float* __restrict__ hist,
           const float* __restrict__ gap,   const float* __restrict__ W_ih,
           const float* __restrict__ W_hh,  const float* __restrict__ b_ih,
           const float* __restrict__ b_hh,  const float* __restrict__ W1,
           const float* __restrict__ b1,    const float* __restrict__ W2,
           const float* __restrict__ b2,    float* __restrict__ out) {
    extern __shared__ char smraw[];
    SMem* s = reinterpret_cast<SMem*>(smraw);

    const int tid  = threadIdx.x;
    const int u    = tid & 63;            // hidden unit
    const int q    = tid >> 6;            // group / row block (0..7)
    const int lane = tid & 31;
    const int wh   = (tid >> 5) & 1;      // warp half within group (u<32 vs u>=32)
    const int blockRow = blockIdx.x * ROWS_PER_CTA;
    const int R = blockRow + 8 * q;       // rows R..R+7

    // ---- stage weights (transposed, gate-packed) ----
    for (int idx = tid; idx < 76 * 64; idx += NTHREADS) {
        int k = idx >> 6, uu = idx & 63;
        float4 w;
        if (k < 12) {
            w.x = W_ih[uu * 12 + k];
            w.y = W_ih[(64 + uu) * 12 + k];
            w.z = W_ih[(128 + uu) * 12 + k];
            w.w = W_ih[(192 + uu) * 12 + k];
        } else {
            int kk = k - 12;
            w.x = W_hh[uu * 64 + kk];
            w.y = W_hh[(64 + uu) * 64 + kk];
            w.z = W_hh[(128 + uu) * 64 + kk];
            w.w = W_hh[(192 + uu) * 64 + kk];
        }
        s->wpack[k][uu] = w;
    }
    for (int idx = tid; idx < 64 * 64; idx += NTHREADS) {
        int uu = idx >> 6, k = idx & 63;
        s->w1t[k][uu] = W1[idx];
    }
    // h0 = 0 in phase 0 (k = 12..75), both sets, all 8 q's
    for (int idx = tid; idx < 64 * 8; idx += NTHREADS) {
        int k = idx >> 3, qq = idx & 7;
        s->xbuf[0][(12 + k) * 21 + qq]      = make_float4(0.f, 0.f, 0.f, 0.f);
        s->xbuf[0][(12 + k) * 21 + 10 + qq] = make_float4(0.f, 0.f, 0.f, 0.f);
    }
    // ---- copy hist_x into out[:, :64, :] ----
    for (int idx = tid; idx < ROWS_PER_CTA * 192; idx += NTHREADS) {
        int rl = idx / 192, j = idx % 192;
        out[(size_t)(blockRow + rl) * OUTSTR + j] = hist[(size_t)(blockRow + rl) * 192 + j];
    }

    const float bi = b_ih[u] + b_hh[u];
    const float bf = b_ih[64 + u] + b_hh[64 + u];
    const float bg = b_ih[128 + u] + b_hh[128 + u];
    const float bo = b_ih[192 + u] + b_hh[192 + u];
    const float b1v = b1[u];
    const float w2v = W2[u];
    const float b2v = b2[0];

    float2 c4[4], h4[4], dist4[4], pfv[4];
#pragma unroll
    for (int p = 0; p < 4; ++p) {
        c4[p] = make_float2(0.f, 0.f);
        dist4[p] = make_float2(0.f, 0.f);
        pfv[p] = make_float2(0.f, 0.f);
    }

    // ---- prefetchers: only u<12 threads touch global memory ----
    auto pre_cond = [&](int j) {
        if (u < 4) {
            int ch = (u == 3) ? 2 : u;      // u==3 tracks ch2 for the dist cumsum
#pragma unroll
            for (int p = 0; p < 4; ++p) {
                const float* hp = hist + (size_t)(R + 2 * p) * 192 + j * 3 + ch;
                pfv[p].x = hp[0];
                pfv[p].y = hp[192];
            }
        } else if (u < 12) {
            int ch = u - 4;
#pragma unroll
            for (int p = 0; p < 4; ++p) {
                const float* np = noise + (size_t)(R + 2 * p) * 2048 + j * 8 + ch;
                pfv[p].x = np[0];
                pfv[p].y = np[2048];
            }
        }
    };
    auto pre_gen = [&](int t) {
        if (u < 2) {
#pragma unroll
            for (int p = 0; p < 4; ++p) {
                const float* gp = gap + (size_t)(R + 2 * p) * 386 + t * 2 + u;
                pfv[p].x = gp[0];
                pfv[p].y = gp[386];
            }
        } else if (u >= 4 && u < 12) {
            if (t < 192) {
                int ch = u - 4;
#pragma unroll
                for (int p = 0; p < 4; ++p) {
                    const float* np = noise + (size_t)(R + 2 * p) * 2048 + (64 + t) * 8 + ch;
                    pfv[p].x = np[0];
                    pfv[p].y = np[2048];
                }
            } else {
#pragma unroll
                for (int p = 0; p < 4; ++p) pfv[p] = make_float2(0.f, 0.f);
            }
        }
    };
    auto write_x4 = [&](int ph, int k, const float2 v[4]) {
        float4* dst = &s->xbuf[ph][k * 21 + q];
        dst[0]  = make_float4(v[0].x, v[0].y, v[1].x, v[1].y);
        dst[10] = make_float4(v[2].x, v[2].y, v[3].x, v[3].y);
    };

    pre_cond(0);
    __syncthreads();   // staging + h0 visible to all groups (last full-CTA barrier)

    // ================= conditioning (64 steps, 1 group-barrier each) =================
    for (int j = 0; j < 64; ++j) {
        int ph = j & 1;
        if (u == 3) {                     // dist = inclusive cumsum of hist ch2
#pragma unroll
            for (int p = 0; p < 4; ++p) {
                dist4[p].x += pfv[p].x;
                dist4[p].y += pfv[p].y;
            }
            write_x4(ph, 3, dist4);
        } else if (u < 12) {
            write_x4(ph, u, pfv);
        }
        bar_grp(q);                       // inputs + previous h visible (own group)
        if (j < 63) pre_cond(j + 1); else pre_gen(0);
        lstm_step4<false>(s, u, q, ph, nullptr, nullptr, bi, bf, bg, bo, c4, h4);
        write_x4(ph ^ 1, 12 + u, h4);
    }
    bar_grp(q);   // last h (phase 0) + last dist (phase 1) visible

    // all threads pick up final dist from phase 1, k=3 (own q)
    {
        float4 v0 = s->xbuf[1][3 * 21 + q];
        float4 v1 = s->xbuf[1][3 * 21 + 10 + q];
        dist4[0] = make_float2(v0.x, v0.y);
        dist4[1] = make_float2(v0.z, v0.w);
        dist4[2] = make_float2(v1.x, v1.y);
        dist4[3] = make_float2(v1.z, v1.w);
    }

    // ================= generation (193 steps, 2 group-barriers each) =================
    for (int t = 0; t <= 192; ++t) {
        int ph = t & 1;
        // --- MLP head: a[u][row] = b1 + sum_k h[k][row]*W1[u][k] ---
        float2 az0 = make_float2(b1v, b1v), az1 = az0, az2 = az0, az3 = az0;
        {
            const float*  w1p = &s->w1t[0][u];
            const float4* hp4 = &s->xbuf[ph][12 * 21 + q];
#pragma unroll 4
            for (int k = 0; k < 64; ++k) {
                float wv = w1p[k * 64];
                float4 X0 = hp4[k * 21], X1 = hp4[k * 21 + 10];
                gate4(wv, make_float2(X0.x, X0.y), make_float2(X0.z, X0.w),
                      make_float2(X1.x, X1.y), make_float2(X1.z, X1.w),
                      az0, az1, az2, az3);
            }
        }
        float2 part[4];
        part[0] = make_float2(tanha(az0.x) * w2v, tanha(az0.y) * w2v);
        part[1] = make_float2(tanha(az1.x) * w2v, tanha(az1.y) * w2v);
        part[2] = make_float2(tanha(az2.x) * w2v, tanha(az2.y) * w2v);
        part[3] = make_float2(tanha(az3.x) * w2v, tanha(az3.y) * w2v);
        // reduce over this warp's 32 u's (all lanes share q)
#pragma unroll
        for (int p = 0; p < 4; ++p) {
#pragma unroll
            for (int m = 16; m >= 1; m >>= 1) {
                part[p].x += __shfl_xor_sync(0xffffffffu, part[p].x, m);
                part[p].y += __shfl_xor_sync(0xffffffffu, part[p].y, m);
            }
        }
        if (lane == 0) {
#pragma unroll
            for (int p = 0; p < 4; ++p) s->zhalf[q][wh][p] = part[p];
        }
        // write gap/noise inputs for this step before the same barrier
        if (u < 2 || (u >= 4 && u < 12)) write_x4(ph, u, pfv);
        bar_grp(q);                       // zhalf + x inputs visible (own group)
        // every thread computes dp for its rows (redundant but cheap)
        float2 dp[4];
#pragma unroll
        for (int p = 0; p < 4; ++p) {
            float2 za = s->zhalf[q][0][p];
            float2 zb = s->zhalf[q][1][p];
            dp[p].x = 24.f * tanha(za.x + zb.x + b2v);
            dp[p].y = 24.f * tanha(za.y + zb.y + b2v);
            dist4[p].x += dp[p].x;
            dist4[p].y += dp[p].y;
        }
        int trow = (64 + t) * 3;
        if (u < 2) {
#pragma unroll
            for (int p = 0; p < 4; ++p) {
                out[(size_t)(R + 2 * p) * OUTSTR + trow + u] = pfv[p].x;
                out[(size_t)(R + 2 * p + 1) * OUTSTR + trow + u] = pfv[p].y;
            }
        } else if (u == 2) {
#pragma unroll
            for (int p = 0; p < 4; ++p) {
                out[(size_t)(R + 2 * p) * OUTSTR + trow + 2] = dp[p].x;
                out[(size_t)(R + 2 * p + 1) * OUTSTR + trow + 2] = dp[p].y;
            }
        }
        if (t == 192) break;              // last LSTM update is dead in the reference
        pre_gen(t + 1);
        lstm_step4<true>(s, u, q, ph, dp, dist4, bi, bf, bg, bo, c4, h4);
        write_x4(ph ^ 1, 12 + u, h4);
        bar_grp(q);                       // h visible for next MLP (own group)
    }
}

extern "C" void kernel_launch(void* const* d_in, const int* in_sizes, int n_in,
                              void* d_out, int out_size) {
    const float* noise = (const float*)d_in[0];
    const float* hist  = (const float*)d_in[1];
    const float* gap   = (const float*)d_in[2];
    const float* W_ih  = (const float*)d_in[3];
    const float* W_hh  = (const float*)d_in[4];
    const float* b_ih  = (const float*)d_in[5];
    const float* b_hh  = (const float*)d_in[6];
    const float* W1    = (const float*)d_in[7];
    const float* b1    = (const float*)d_in[8];
    const float* W2    = (const float*)d_in[9];
    const float* b2    = (const float*)d_in[10];
    float* out = (float*)d_out;

    size_t smem = sizeof(SMem);
    cudaFuncSetAttribute(lstm_fused, cudaFuncAttributeMaxDynamicSharedMemorySize, (int)smem);
    lstm_fused<<<NCTA, NTHREADS, smem>>>(noise, hist, gap, W_ih, W_hh, b_ih, b_hh,
                                         W1, b1, W2, b2, out);
}

// round 15
// speedup vs baseline: 1.0835x; 1.0835x over previous
#include <cuda_runtime.h>

#define NTHREADS 256
#define ROWS_PER_CTA 64
#define NCTA 128          // 8192 / 64
#define OUTSTR 771        // 257*3

// R12 base: two independent halves of 128 threads (rows 0-31 / 32-63).
// u = htid & 63 (hidden unit), q = 2*half + (htid>>6). 16 rows/thread (8 pairs).
// Gen step restructured: MLP fused into gate h-loop; gates split across the
// z-barrier (k=2,3 after); inputs written at step end with pfv(t+1).
struct SMem {
    float4 wpack[76][64];   // {Wi,Wf,Wg,Wo}[.,k] for unit u        (77824 B)
    float4 xbuf[2][76*21];  // [phase][k*21 + set*5 + q]            (51072 B)
    float  w1t[64][64];     // w1t[k][u] = W1[u][k]                 (16384 B)
    float2 zhalf[4][2][8];  // [q][warp-half][pair]                 (  512 B)
};

__device__ __forceinline__ void bar_half(int half) {
    asm volatile("bar.sync %0, 128;" :: "r"(half + 1) : "memory");
}

__device__ __forceinline__ float tanha(float x) {
    float r;
    asm("tanh.approx.f32 %0, %1;" : "=f"(r) : "f"(x));
    return r;
}
__device__ __forceinline__ float siga(float x) {
    return fmaf(0.5f, tanha(0.5f * x), 0.5f);
}

// 4 accumulators += pair-vector * scalar, via packed fma.rn.f32x2
__device__ __forceinline__ void gate4(float sw,
                                      float2 p0, float2 p1, float2 p2, float2 p3,
                                      float2& a0, float2& a1, float2& a2, float2& a3) {
    asm("{\n\t"
        ".reg .b64 rb, rx, ra;\n\t"
        "mov.b64 rb, {%8,%8};\n\t"
        "mov.b64 rx, {%9,%10};  mov.b64 ra, {%0,%1}; fma.rn.f32x2 ra, rx, rb, ra; mov.b64 {%0,%1}, ra;\n\t"
        "mov.b64 rx, {%11,%12}; mov.b64 ra, {%2,%3}; fma.rn.f32x2 ra, rx, rb, ra; mov.b64 {%2,%3}, ra;\n\t"
        "mov.b64 rx, {%13,%14}; mov.b64 ra, {%4,%5}; fma.rn.f32x2 ra, rx, rb, ra; mov.b64 {%4,%5}, ra;\n\t"
        "mov.b64 rx, {%15,%16}; mov.b64 ra, {%6,%7}; fma.rn.f32x2 ra, rx, rb, ra; mov.b64 {%6,%7}, ra;\n\t"
        "}"
        : "+f"(a0.x), "+f"(a0.y), "+f"(a1.x), "+f"(a1.y),
          "+f"(a2.x), "+f"(a2.y), "+f"(a3.x), "+f"(a3.y)
        : "f"(sw),
          "f"(p0.x), "f"(p0.y), "f"(p1.x), "f"(p1.y),
          "f"(p2.x), "f"(p2.y), "f"(p3.x), "f"(p3.y));
}

// Full LSTM cell for the conditioning phase (all 76 k from SMEM phase ph).
__device__ __forceinline__ void lstm_cond8(const SMem* s, int u, int q, int ph,
                                           float bi, float bf, float bg, float bo,
                                           float2 c8[8], float2 h8[8]) {
    float2 ai[8], af8[8], ag[8], ao[8];
#pragma unroll
    for (int p = 0; p < 8; ++p) {
        ai[p] = make_float2(bi, bi);
        af8[p] = make_float2(bf, bf);
        ag[p] = make_float2(bg, bg);
        ao[p] = make_float2(bo, bo);
    }
    const float4* wp = &s->wpack[0][u];
    const float4* xp = &s->xbuf[ph][q];

    auto doK = [&](float4 w, float4 X0, float4 X1, float4 X2, float4 X3) {
        float2 p0 = make_float2(X0.x, X0.y), p1 = make_float2(X0.z, X0.w);
        float2 p2 = make_float2(X1.x, X1.y), p3 = make_float2(X1.z, X1.w);
        float2 p4 = make_float2(X2.x, X2.y), p5 = make_float2(X2.z, X2.w);
        float2 p6 = make_float2(X3.x, X3.y), p7 = make_float2(X3.z, X3.w);
        gate4(w.x, p0, p1, p2, p3, ai[0], ai[1], ai[2], ai[3]);
        gate4(w.x, p4, p5, p6, p7, ai[4], ai[5], ai[6], ai[7]);
        gate4(w.y, p0, p1, p2, p3, af8[0], af8[1], af8[2], af8[3]);
        gate4(w.y, p4, p5, p6, p7, af8[4], af8[5], af8[6], af8[7]);
        gate4(w.z, p0, p1, p2, p3, ag[0], ag[1], ag[2], ag[3]);
        gate4(w.z, p4, p5, p6, p7, ag[4], ag[5], ag[6], ag[7]);
        gate4(w.w, p0, p1, p2, p3, ao[0], ao[1], ao[2], ao[3]);
        gate4(w.w, p4, p5, p6, p7, ao[4], ao[5], ao[6], ao[7]);
    };

    doK(wp[0], xp[0], xp[5], xp[10], xp[15]);
    doK(wp[64], xp[21], xp[26], xp[31], xp[36]);
    doK(wp[2 * 64], xp[42], xp[47], xp[52], xp[57]);
    doK(wp[3 * 64], xp[63], xp[68], xp[73], xp[78]);
    float4 wc = wp[4 * 64];
    float4 a0 = xp[4 * 21], a1 = xp[4 * 21 + 5], a2 = xp[4 * 21 + 10], a3 = xp[4 * 21 + 15];
#pragma unroll 4
    for (int k = 4; k < 75; ++k) {
        float4 wn = wp[(k + 1) * 64];
        float4 n0 = xp[(k + 1) * 21],      n1 = xp[(k + 1) * 21 + 5];
        float4 n2 = xp[(k + 1) * 21 + 10], n3 = xp[(k + 1) * 21 + 15];
        doK(wc, a0, a1, a2, a3);
        wc = wn; a0 = n0; a1 = n1; a2 = n2; a3 = n3;
    }
    doK(wc, a0, a1, a2, a3);

#pragma unroll
    for (int p = 0; p < 8; ++p) {
        float ix = siga(ai[p].x), fx = siga(af8[p].x), gx = tanha(ag[p].x), ox = siga(ao[p].x);
        c8[p].x = fmaf(fx, c8[p].x, ix * gx);
        h8[p].x = ox * tanha(c8[p].x);
        float iy = siga(ai[p].y), fy = siga(af8[p].y), gy = tanha(ag[p].y), oy = siga(ao[p].y);
        c8[p].y = fmaf(fy, c8[p].y, iy * gy);
        h8[p].y = oy * tanha(c8[p].y);
    }
}

__global__ void __launch_bounds__(NTHREADS, 1)
lstm_fused(const float* __restrict__ noise, const float* __restrict__ hist,
           const float* __restrict__ gap,   const float* __restrict__ W_ih,
           const float* __restrict__ W_hh,  const float* __restrict__ b_ih,
           const float* __restrict__ b_hh,  const float* __restrict__ W1,
           const float* __restrict__ b1,    const float* __restrict__ W2,
           const float* __restrict__ b2,    float* __restrict__ out) {
    extern __shared__ char smraw[];
    SMem* s = reinterpret_cast<SMem*>(smraw);

    const int tid  = threadIdx.x;
    const int half = tid >> 7;               // 0: rows 0-31, 1: rows 32-63
    const int htid = tid & 127;
    const int u    = htid & 63;              // hidden unit
    const int q    = 2 * half + (htid >> 6); // row group (0..3)
    const int lane = tid & 31;
    const int wh   = (htid >> 5) & 1;        // warp half within q
    const int blockRow = blockIdx.x * ROWS_PER_CTA;
    const int R = blockRow + 16 * q;         // rows R..R+15

    // ---- stage weights (transposed, gate-packed) ----
    for (int idx = tid; idx < 76 * 64; idx += NTHREADS) {
        int k = idx >> 6, uu = idx & 63;
        float4 w;
        if (k < 12) {
            w.x = W_ih[uu * 12 + k];
            w.y = W_ih[(64 + uu) * 12 + k];
            w.z = W_ih[(128 + uu) * 12 + k];
            w.w = W_ih[(192 + uu) * 12 + k];
        } else {
            int kk = k - 12;
            w.x = W_hh[uu * 64 + kk];
            w.y = W_hh[(64 + uu) * 64 + kk];
            w.z = W_hh[(128 + uu) * 64 + kk];
            w.w = W_hh[(192 + uu) * 64 + kk];
        }
        s->wpack[k][uu] = w;
    }
    for (int idx = tid; idx < 64 * 64; idx += NTHREADS) {
        int uu = idx >> 6, k = idx & 63;
        s->w1t[k][uu] = W1[idx];
    }
    // h0 = 0 in phase 0 (k = 12..75)
    for (int idx = tid; idx < 64 * 4; idx += NTHREADS) {
        int k = idx >> 2, st = idx & 3;
#pragma unroll
        for (int qq = 0; qq < 4; ++qq)
            s->xbuf[0][(12 + k) * 21 + st * 5 + qq] = make_float4(0.f, 0.f, 0.f, 0.f);
    }
    // ---- copy hist_x into out[:, :64, :] ----
    for (int idx = tid; idx < ROWS_PER_CTA * 192; idx += NTHREADS) {
        int rl = idx / 192, j = idx % 192;
        out[(size_t)(blockRow + rl) * OUTSTR + j] = hist[(size_t)(blockRow + rl) * 192 + j];
    }

    const float bi = b_ih[u] + b_hh[u];
    const float bf = b_ih[64 + u] + b_hh[64 + u];
    const float bg = b_ih[128 + u] + b_hh[128 + u];
    const float bo = b_ih[192 + u] + b_hh[192 + u];
    const float b1v = b1[u];
    const float w2v = W2[u];
    const float b2v = b2[0];

    float2 c8[8], h8[8], dist8[8], pfv[8];
#pragma unroll
    for (int p = 0; p < 8; ++p) {
        c8[p] = make_float2(0.f, 0.f);
        dist8[p] = make_float2(0.f, 0.f);
        pfv[p] = make_float2(0.f, 0.f);
    }

    // ---- prefetchers: only u<12 threads touch global memory ----
    auto pre_cond = [&](int j) {
        if (u < 4) {
            int ch = (u == 3) ? 2 : u;      // u==3 tracks ch2 for the dist cumsum
#pragma unroll
            for (int p = 0; p < 8; ++p) {
                const float* hp = hist + (size_t)(R + 2 * p) * 192 + j * 3 + ch;
                pfv[p].x = hp[0];
                pfv[p].y = hp[192];
            }
        } else if (u < 12) {
            int ch = u - 4;
#pragma unroll
            for (int p = 0; p < 8; ++p) {
                const float* np = noise + (size_t)(R + 2 * p) * 2048 + j * 8 + ch;
                pfv[p].x = np[0];
                pfv[p].y = np[2048];
            }
        }
    };
    auto pre_gen = [&](int t) {
        if (u < 2) {
#pragma unroll
            for (int p = 0; p < 8; ++p) {
                const float* gp = gap + (size_t)(R + 2 * p) * 386 + t * 2 + u;
                pfv[p].x = gp[0];
                pfv[p].y = gp[386];
            }
        } else if (u >= 4 && u < 12) {
            if (t < 192) {
                int ch = u - 4;
#pragma unroll
                for (int p = 0; p < 8; ++p) {
                    const float* np = noise + (size_t)(R + 2 * p) * 2048 + (64 + t) * 8 + ch;
                    pfv[p].x = np[0];
                    pfv[p].y = np[2048];
                }
            } else {
#pragma unroll
                for (int p = 0; p < 8; ++p) pfv[p] = make_float2(0.f, 0.f);
            }
        }
    };
    auto write_x4 = [&](int ph, int k, const float2 v[8]) {
        float4* dst = &s->xbuf[ph][k * 21 + q];
        dst[0]  = make_float4(v[0].x, v[0].y, v[1].x, v[1].y);
        dst[5]  = make_float4(v[2].x, v[2].y, v[3].x, v[3].y);
        dst[10] = make_float4(v[4].x, v[4].y, v[5].x, v[5].y);
        dst[15] = make_float4(v[6].x, v[6].y, v[7].x, v[7].y);
    };

    pre_cond(0);
    __syncthreads();   // staging + h0 visible (last full-CTA barrier)

    // ================= conditioning (64 steps, 1 half-barrier each) =================
    for (int j = 0; j < 64; ++j) {
        int ph = j & 1;
        if (u == 3) {                     // dist = inclusive cumsum of hist ch2
#pragma unroll
            for (int p = 0; p < 8; ++p) {
                dist8[p].x += pfv[p].x;
                dist8[p].y += pfv[p].y;
            }
            write_x4(ph, 3, dist8);
        } else if (u < 12) {
            write_x4(ph, u, pfv);
        }
        bar_half(half);                   // inputs + previous h visible (own half)
        if (j < 63) pre_cond(j + 1); else pre_gen(0);
        lstm_cond8(s, u, q, ph, bi, bf, bg, bo, c8, h8);
        write_x4(ph ^ 1, 12 + u, h8);
    }
    // write gen t=0 inputs into phase 0 (pfv holds pre_gen(0))
    if (u < 2 || (u >= 4 && u < 12)) write_x4(0, u, pfv);
    bar_half(half);   // h (phase 0), dist (phase 1), t=0 inputs visible

    // all threads pick up final dist from phase 1, k=3 (own q)
    {
        const float4* src = &s->xbuf[1][3 * 21 + q];
#pragma unroll
        for (int st = 0; st < 4; ++st) {
            float4 v = src[st * 5];
            dist8[2 * st]     = make_float2(v.x, v.y);
            dist8[2 * st + 1] = make_float2(v.z, v.w);
        }
    }

    // ================= generation (192 full steps + MLP epilogue) =================
    for (int t = 0; t < 192; ++t) {
        int ph = t & 1;
        int trow = (64 + t) * 3;
        // gap outputs for step t (pfv holds step-t values)
        if (u < 2) {
#pragma unroll
            for (int p = 0; p < 8; ++p) {
                out[(size_t)(R + 2 * p) * OUTSTR + trow + u] = pfv[p].x;
                out[(size_t)(R + 2 * p + 1) * OUTSTR + trow + u] = pfv[p].y;
            }
        }
        pre_gen(t + 1);                   // pfv now holds step t+1 inputs

        // accumulators: gates + MLP
        float2 ai[8], af8[8], ag[8], ao[8], az[8];
#pragma unroll
        for (int p = 0; p < 8; ++p) {
            ai[p] = make_float2(bi, bi);
            af8[p] = make_float2(bf, bf);
            ag[p] = make_float2(bg, bg);
            ao[p] = make_float2(bo, bo);
            az[p] = make_float2(b1v, b1v);
        }
        auto doGates = [&](float4 w, float2 p0, float2 p1, float2 p2, float2 p3,
                           float2 p4, float2 p5, float2 p6, float2 p7) {
            gate4(w.x, p0, p1, p2, p3, ai[0], ai[1], ai[2], ai[3]);
            gate4(w.x, p4, p5, p6, p7, ai[4], ai[5], ai[6], ai[7]);
            gate4(w.y, p0, p1, p2, p3, af8[0], af8[1], af8[2], af8[3]);
            gate4(w.y, p4, p5, p6, p7, af8[4], af8[5], af8[6], af8[7]);
            gate4(w.z, p0, p1, p2, p3, ag[0], ag[1], ag[2], ag[3]);
            gate4(w.z, p4, p5, p6, p7, ag[4], ag[5], ag[6], ag[7]);
            gate4(w.w, p0, p1, p2, p3, ao[0], ao[1], ao[2], ao[3]);
            gate4(w.w, p4, p5, p6, p7, ao[4], ao[5], ao[6], ao[7]);
        };

        // ---- fused h loop: gates (k=12..75) + MLP, pipelined ----
        {
            const float4* wp  = &s->wpack[12][u];
            const float*  w1p = &s->w1t[0][u];
            const float4* xp  = &s->xbuf[ph][12 * 21 + q];
            float4 wc = wp[0];
            float  w1c = w1p[0];
            float4 a0 = xp[0], a1 = xp[5], a2 = xp[10], a3 = xp[15];
#pragma unroll 4
            for (int kh = 0; kh < 63; ++kh) {
                float4 wn = wp[(kh + 1) * 64];
                float  w1n = w1p[(kh + 1) * 64];
                float4 n0 = xp[(kh + 1) * 21],      n1 = xp[(kh + 1) * 21 + 5];
                float4 n2 = xp[(kh + 1) * 21 + 10], n3 = xp[(kh + 1) * 21 + 15];
                float2 p0 = make_float2(a0.x, a0.y), p1 = make_float2(a0.z, a0.w);
                float2 p2 = make_float2(a1.x, a1.y), p3 = make_float2(a1.z, a1.w);
                float2 p4 = make_float2(a2.x, a2.y), p5 = make_float2(a2.z, a2.w);
                float2 p6 = make_float2(a3.x, a3.y), p7 = make_float2(a3.z, a3.w);
                doGates(wc, p0, p1, p2, p3, p4, p5, p6, p7);
                gate4(w1c, p0, p1, p2, p3, az[0], az[1], az[2], az[3]);
                gate4(w1c, p4, p5, p6, p7, az[4], az[5], az[6], az[7]);
                wc = wn; w1c = w1n; a0 = n0; a1 = n1; a2 = n2; a3 = n3;
            }
            float2 p0 = make_float2(a0.x, a0.y), p1 = make_float2(a0.z, a0.w);
            float2 p2 = make_float2(a1.x, a1.y), p3 = make_float2(a1.z, a1.w);
            float2 p4 = make_float2(a2.x, a2.y), p5 = make_float2(a2.z, a2.w);
            float2 p6 = make_float2(a3.x, a3.y), p7 = make_float2(a3.z, a3.w);
            doGates(wc, p0, p1, p2, p3, p4, p5, p6, p7);
            gate4(w1c, p0, p1, p2, p3, az[0], az[1], az[2], az[3]);
            gate4(w1c, p4, p5, p6, p7, az[4], az[5], az[6], az[7]);
        }
        // ---- input ks: 0,1,4..11 (from xbuf, written at end of prev step) ----
        {
            const float4* xp = &s->xbuf[ph][q];
            const float4* wp = &s->wpack[0][u];
            auto doKx = [&](int k) {
                float4 w = wp[k * 64];
                float4 X0 = xp[k * 21], X1 = xp[k * 21 + 5];
                float4 X2 = xp[k * 21 + 10], X3 = xp[k * 21 + 15];
                doGates(w, make_float2(X0.x, X0.y), make_float2(X0.z, X0.w),
                        make_float2(X1.x, X1.y), make_float2(X1.z, X1.w),
                        make_float2(X2.x, X2.y), make_float2(X2.z, X2.w),
                        make_float2(X3.x, X3.y), make_float2(X3.z, X3.w));
            };
            doKx(0); doKx(1);
#pragma unroll
            for (int k = 4; k < 12; ++k) doKx(k);
        }
        // ---- z partials + warp reduce + cross-warp exchange ----
        float2 part[8];
#pragma unroll
        for (int p = 0; p < 8; ++p)
            part[p] = make_float2(tanha(az[p].x) * w2v, tanha(az[p].y) * w2v);
#pragma unroll
        for (int p = 0; p < 8; ++p) {
#pragma unroll
            for (int m = 16; m >= 1; m >>= 1) {
                part[p].x += __shfl_xor_sync(0xffffffffu, part[p].x, m);
                part[p].y += __shfl_xor_sync(0xffffffffu, part[p].y, m);
            }
        }
        if (lane == 0) {
#pragma unroll
            for (int p = 0; p < 8; ++p) s->zhalf[q][wh][p] = part[p];
        }
        bar_half(half);                   // zhalf visible (own half)

        // ---- dp / dist, finish gates (k=2,3), nonlinearities ----
        float2 dp[8];
#pragma unroll
        for (int p = 0; p < 8; ++p) {
            float2 za = s->zhalf[q][0][p];
            float2 zb = s->zhalf[q][1][p];
            dp[p].x = 24.f * tanha(za.x + zb.x + b2v);
            dp[p].y = 24.f * tanha(za.y + zb.y + b2v);
            dist8[p].x += dp[p].x;
            dist8[p].y += dp[p].y;
        }
        {
            float4 w2p = s->wpack[2][u];
            float4 w3p = s->wpack[3][u];
            gate4(w2p.x, dp[0], dp[1], dp[2], dp[3], ai[0], ai[1], ai[2], ai[3]);
            gate4(w2p.x, dp[4], dp[5], dp[6], dp[7], ai[4], ai[5], ai[6], ai[7]);
            gate4(w2p.y, dp[0], dp[1], dp[2], dp[3], af8[0], af8[1], af8[2], af8[3]);
            gate4(w2p.y, dp[4], dp[5], dp[6], dp[7], af8[4], af8[5], af8[6], af8[7]);
            gate4(w2p.z, dp[0], dp[1], dp[2], dp[3], ag[0], ag[1], ag[2], ag[3]);
            gate4(w2p.z, dp[4], dp[5], dp[6], dp[7], ag[4], ag[5], ag[6], ag[7]);
            gate4(w2p.w, dp[0], dp[1], dp[2], dp[3], ao[0], ao[1], ao[2], ao[3]);
            gate4(w2p.w, dp[4], dp[5], dp[6], dp[7], ao[4], ao[5], ao[6], ao[7]);
            gate4(w3p.x, dist8[0], dist8[1], dist8[2], dist8[3], ai[0], ai[1], ai[2], ai[3]);
            gate4(w3p.x, dist8[4], dist8[5], dist8[6], dist8[7], ai[4], ai[5], ai[6], ai[7]);
            gate4(w3p.y, dist8[0], dist8[1], dist8[2], dist8[3], af8[0], af8[1], af8[2], af8[3]);
            gate4(w3p.y, dist8[4], dist8[5], dist8[6], dist8[7], af8[4], af8[5], af8[6], af8[7]);
            gate4(w3p.z, dist8[0], dist8[1], dist8[2], dist8[3], ag[0], ag[1], ag[2], ag[3]);
            gate4(w3p.z, dist8[4], dist8[5], dist8[6], dist8[7], ag[4], ag[5], ag[6], ag[7]);
            gate4(w3p.w, dist8[0], dist8[1], dist8[2], dist8[3], ao[0], ao[1], ao[2], ao[3]);
            gate4(w3p.w, dist8[4], dist8[5], dist8[6], dist8[7], ao[4], ao[5], ao[6], ao[7]);
        }
#pragma unroll
        for (int p = 0; p < 8; ++p) {
            float ix = siga(ai[p].x), fx = siga(af8[p].x), gx = tanha(ag[p].x), ox = siga(ao[p].x);
            c8[p].x = fmaf(fx, c8[p].x, ix * gx);
            h8[p].x = ox * tanha(c8[p].x);
            float iy = siga(ai[p].y), fy = siga(af8[p].y), gy = tanha(ag[p].y), oy = siga(ao[p].y);
            c8[p].y = fmaf(fy, c8[p].y, iy * gy);
            h8[p].y = oy * tanha(c8[p].y);
        }
        // dp outputs
        if (u == 2) {
#pragma unroll
            for (int p = 0; p < 8; ++p) {
                out[(size_t)(R + 2 * p) * OUTSTR + trow + 2] = dp[p].x;
                out[(size_t)(R + 2 * p + 1) * OUTSTR + trow + 2] = dp[p].y;
            }
        }
        // write h + step t+1 inputs into phase ph^1
        write_x4(ph ^ 1, 12 + u, h8);
        if (u < 2 || (u >= 4 && u < 12)) write_x4(ph ^ 1, u, pfv);
        bar_half(half);                   // visible for next step (own half)
    }

    // ---- epilogue t=192: outputs only (gap + dp from MLP on final h) ----
    {
        const int ph = 0;                 // 192 & 1
        const int trow = (64 + 192) * 3;
        if (u < 2) {
#pragma unroll
            for (int p = 0; p < 8; ++p) {
                out[(size_t)(R + 2 * p) * OUTSTR + trow + u] = pfv[p].x;
                out[(size_t)(R + 2 * p + 1) * OUTSTR + trow + u] = pfv[p].y;
            }
        }
        float2 az[8];
#pragma unroll
        for (int p = 0; p < 8; ++p) az[p] = make_float2(b1v, b1v);
        {
            const float*  w1p = &s->w1t[0][u];
            const float4* xp  = &s->xbuf[ph][12 * 21 + q];
#pragma unroll 4
            for (int k = 0; k < 64; ++k) {
                float wv = w1p[k * 64];
                float4 X0 = xp[k * 21],      X1 = xp[k * 21 + 5];
                float4 X2 = xp[k * 21 + 10], X3 = xp[k * 21 + 15];
                gate4(wv, make_float2(X0.x, X0.y), make_float2(X0.z, X0.w),
                      make_float2(X1.x, X1.y), make_float2(X1.z, X1.w),
                      az[0], az[1], az[2], az[3]);
                gate4(wv, make_float2(X2.x, X2.y), make_float2(X2.z, X2.w),
                      make_float2(X3.x, X3.y), make_float2(X3.z, X3.w),
                      az[4], az[5], az[6], az[7]);
            }
        }
        float2 part[8];
#pragma unroll
        for (int p = 0; p < 8; ++p)
            part[p] = make_float2(tanha(az[p].x) * w2v, tanha(az[p].y) * w2v);
#pragma unroll
        for (int p = 0; p < 8; ++p) {
#pragma unroll
            for (int m = 16; m >= 1; m >>= 1) {
                part[p].x += __shfl_xor_sync(0xffffffffu, part[p].x, m);
                part[p].y += __shfl_xor_sync(0xffffffffu, part[p].y, m);
            }
        }
        if (lane == 0) {
#pragma unroll
            for (int p = 0; p < 8; ++p) s->zhalf[q][wh][p] = part[p];
        }
        bar_half(half);
        if (u == 2) {
#pragma unroll
            for (int p = 0; p < 8; ++p) {
                float2 za = s->zhalf[q][0][p];
                float2 zb = s->zhalf[q][1][p];
                float dx = 24.f * tanha(za.x + zb.x + b2v);
                float dy = 24.f * tanha(za.y + zb.y + b2v);
                out[(size_t)(R + 2 * p) * OUTSTR + trow + 2] = dx;
                out[(size_t)(R + 2 * p + 1) * OUTSTR + trow + 2] = dy;
            }
        }
    }
}

extern "C" void kernel_launch(void* const* d_in, const int* in_sizes, int n_in,
                              void* d_out, int out_size) {
    const float* noise = (const float*)d_in[0];
    const float* hist  = (const float*)d_in[1];
    const float* gap   = (const float*)d_in[2];
    const float* W_ih  = (const float*)d_in[3];
    const float* W_hh  = (const float*)d_in[4];
    const float* b_ih  = (const float*)d_in[5];
    const float* b_hh  = (const float*)d_in[6];
    const float* W1    = (const float*)d_in[7];
    const float* b1    = (const float*)d_in[8];
    const float* W2    = (const float*)d_in[9];
    const float* b2    = (const float*)d_in[10];
    float* out = (float*)d_out;

    size_t smem = sizeof(SMem);
    cudaFuncSetAttribute(lstm_fused, cudaFuncAttributeMaxDynamicSharedMemorySize, (int)smem);
    lstm_fused<<<NCTA, NTHREADS, smem>>>(noise, hist, gap, W_ih, W_hh, b_ih, b_hh,
                                         W1, b1, W2, b2, out);
}

// round 17
// speedup vs baseline: 1.2101x; 1.1169x over previous
#include <cuda_runtime.h>

#define NTHREADS 256
#define ROWS_PER_CTA 56
#define NCTA 147          // 147*56 = 8232 >= 8192 (tail clamped)
#define BB 8192
#define OUTSTR 771        // 257*3
#define NP 7              // pairs per thread (14 rows per q-group)

// Two independent halves of 128 threads (rows 0-27 / 28-55 of the CTA).
// u = htid & 63 (hidden unit), q = 2*half + (htid>>6). 14 rows/thread (7 pairs).
// xbuf: float4[2][76*17], slot base k*17 + q*4; slots 0,1,2 = pairs 0-5,
// slot 3 low half = pair 6. k-stride 17 f4 (17 mod 8 == 1 -> conflict-free).
struct SMem {
    float4 wpack[76][64];   // {Wi,Wf,Wg,Wo}[.,k] for unit u        (77824 B)
    float4 xbuf[2][76*17];  // [phase][k*17 + q*4 + slot]           (41344 B)
    float  w1t[64][64];     // w1t[k][u] = W1[u][k]                 (16384 B)
    float2 zhalf[4][2][NP]; // [q][warp-half][pair]                 (  448 B)
};

__device__ __forceinline__ void bar_half(int half) {
    asm volatile("bar.sync %0, 128;" :: "r"(half + 1) : "memory");
}

__device__ __forceinline__ float tanha(float x) {
    float r;
    asm("tanh.approx.f32 %0, %1;" : "=f"(r) : "f"(x));
    return r;
}
__device__ __forceinline__ float siga(float x) {
    return fmaf(0.5f, tanha(0.5f * x), 0.5f);
}

// 4 accumulators += pair-vector * scalar, via packed fma.rn.f32x2
__device__ __forceinline__ void gate4(float sw,
                                      float2 p0, float2 p1, float2 p2, float2 p3,
                                      float2& a0, float2& a1, float2& a2, float2& a3) {
    asm("{\n\t"
        ".reg .b64 rb, rx, ra;\n\t"
        "mov.b64 rb, {%8,%8};\n\t"
        "mov.b64 rx, {%9,%10};  mov.b64 ra, {%0,%1}; fma.rn.f32x2 ra, rx, rb, ra; mov.b64 {%0,%1}, ra;\n\t"
        "mov.b64 rx, {%11,%12}; mov.b64 ra, {%2,%3}; fma.rn.f32x2 ra, rx, rb, ra; mov.b64 {%2,%3}, ra;\n\t"
        "mov.b64 rx, {%13,%14}; mov.b64 ra, {%4,%5}; fma.rn.f32x2 ra, rx, rb, ra; mov.b64 {%4,%5}, ra;\n\t"
        "mov.b64 rx, {%15,%16}; mov.b64 ra, {%6,%7}; fma.rn.f32x2 ra, rx, rb, ra; mov.b64 {%6,%7}, ra;\n\t"
        "}"
        : "+f"(a0.x), "+f"(a0.y), "+f"(a1.x), "+f"(a1.y),
          "+f"(a2.x), "+f"(a2.y), "+f"(a3.x), "+f"(a3.y)
        : "f"(sw),
          "f"(p0.x), "f"(p0.y), "f"(p1.x), "f"(p1.y),
          "f"(p2.x), "f"(p2.y), "f"(p3.x), "f"(p3.y));
}
// 3-accumulator variant
__device__ __forceinline__ void gate3(float sw,
                                      float2 p0, float2 p1, float2 p2,
                                      float2& a0, float2& a1, float2& a2) {
    asm("{\n\t"
        ".reg .b64 rb, rx, ra;\n\t"
        "mov.b64 rb, {%6,%6};\n\t"
        "mov.b64 rx, {%7,%8};   mov.b64 ra, {%0,%1}; fma.rn.f32x2 ra, rx, rb, ra; mov.b64 {%0,%1}, ra;\n\t"
        "mov.b64 rx, {%9,%10};  mov.b64 ra, {%2,%3}; fma.rn.f32x2 ra, rx, rb, ra; mov.b64 {%2,%3}, ra;\n\t"
        "mov.b64 rx, {%11,%12}; mov.b64 ra, {%4,%5}; fma.rn.f32x2 ra, rx, rb, ra; mov.b64 {%4,%5}, ra;\n\t"
        "}"
        : "+f"(a0.x), "+f"(a0.y), "+f"(a1.x), "+f"(a1.y), "+f"(a2.x), "+f"(a2.y)
        : "f"(sw),
          "f"(p0.x), "f"(p0.y), "f"(p1.x), "f"(p1.y), "f"(p2.x), "f"(p2.y));
}

// accumulate one k into 4 gate accumulator sets (7 pairs each).
// NOTE: parameter named W4 (NOT w) so member access .w is not macro-substituted.
#define DO_GATES7(W4, p0,p1,p2,p3,p4,p5,p6, ai, af7, ag, ao)                  \
    do {                                                                      \
        gate4((W4).x, p0, p1, p2, p3, (ai)[0], (ai)[1], (ai)[2], (ai)[3]);    \
        gate3((W4).x, p4, p5, p6, (ai)[4], (ai)[5], (ai)[6]);                 \
        gate4((W4).y, p0, p1, p2, p3, (af7)[0], (af7)[1], (af7)[2], (af7)[3]);\
        gate3((W4).y, p4, p5, p6, (af7)[4], (af7)[5], (af7)[6]);              \
        gate4((W4).z, p0, p1, p2, p3, (ag)[0], (ag)[1], (ag)[2], (ag)[3]);    \
        gate3((W4).z, p4, p5, p6, (ag)[4], (ag)[5], (ag)[6]);                 \
        gate4((W4).w, p0, p1, p2, p3, (ao)[0], (ao)[1], (ao)[2], (ao)[3]);    \
        gate3((W4).w, p4, p5, p6, (ao)[4], (ao)[5], (ao)[6]);                 \
    } while (0)

// Full LSTM cell for the conditioning phase (all 76 k from SMEM phase ph).
__device__ __forceinline__ void lstm_cond7(const SMem* s, int u, int q, int ph,
                                           float bi, float bf, float bg, float bo,
                                           float2 c7[NP], float2 h7[NP]) {
    float2 ai[NP], af7[NP], ag[NP], ao[NP];
#pragma unroll
    for (int p = 0; p < NP; ++p) {
        ai[p] = make_float2(bi, bi);
        af7[p] = make_float2(bf, bf);
        ag[p] = make_float2(bg, bg);
        ao[p] = make_float2(bo, bo);
    }
    const float4* wp = &s->wpack[0][u];
    const float4* xp = &s->xbuf[ph][q * 4];

    auto doK = [&](float4 wk, float4 X0, float4 X1, float4 X2, float2 X3) {
        float2 p0 = make_float2(X0.x, X0.y), p1 = make_float2(X0.z, X0.w);
        float2 p2 = make_float2(X1.x, X1.y), p3 = make_float2(X1.z, X1.w);
        float2 p4 = make_float2(X2.x, X2.y), p5 = make_float2(X2.z, X2.w);
        DO_GATES7(wk, p0, p1, p2, p3, p4, p5, X3, ai, af7, ag, ao);
    };
    auto ldx3 = [&](int k) { return *reinterpret_cast<const float2*>(xp + k * 17 + 3); };

    doK(wp[0], xp[0], xp[1], xp[2], ldx3(0));
    doK(wp[64], xp[17], xp[18], xp[19], ldx3(1));
    doK(wp[2 * 64], xp[34], xp[35], xp[36], ldx3(2));
    doK(wp[3 * 64], xp[51], xp[52], xp[53], ldx3(3));
    float4 wc = wp[4 * 64];
    float4 a0 = xp[4 * 17], a1 = xp[4 * 17 + 1], a2 = xp[4 * 17 + 2];
    float2 a3 = ldx3(4);
#pragma unroll 4
    for (int k = 4; k < 75; ++k) {
        float4 wn = wp[(k + 1) * 64];
        float4 n0 = xp[(k + 1) * 17], n1 = xp[(k + 1) * 17 + 1], n2 = xp[(k + 1) * 17 + 2];
        float2 n3 = ldx3(k + 1);
        doK(wc, a0, a1, a2, a3);
        wc = wn; a0 = n0; a1 = n1; a2 = n2; a3 = n3;
    }
    doK(wc, a0, a1, a2, a3);

#pragma unroll
    for (int p = 0; p < NP; ++p) {
        float ix = siga(ai[p].x), fx = siga(af7[p].x), gx = tanha(ag[p].x), ox = siga(ao[p].x);
        c7[p].x = fmaf(fx, c7[p].x, ix * gx);
        h7[p].x = ox * tanha(c7[p].x);
        float iy = siga(ai[p].y), fy = siga(af7[p].y), gy = tanha(ag[p].y), oy = siga(ao[p].y);
        c7[p].y = fmaf(fy, c7[p].y, iy * gy);
        h7[p].y = oy * tanha(c7[p].y);
    }
}

__global__ void __launch_bounds__(NTHREADS, 1)
lstm_fused(const float* __restrict__ noise, const float* __restrict__ hist,
           const float* __restrict__ gap,   const float* __restrict__ W_ih,
           const float* __restrict__ W_hh,  const float* __restrict__ b_ih,
           const float* __restrict__ b_hh,  const float* __restrict__ W1,
           const float* __restrict__ b1,    const float* __restrict__ W2,
           const float* __restrict__ b2,    float* __restrict__ out) {
    extern __shared__ char smraw[];
    SMem* s = reinterpret_cast<SMem*>(smraw);

    const int tid  = threadIdx.x;
    const int half = tid >> 7;               // 0: rows 0-27, 1: rows 28-55
    const int htid = tid & 127;
    const int u    = htid & 63;              // hidden unit
    const int q    = 2 * half + (htid >> 6); // row group (0..3)
    const int lane = tid & 31;
    const int wh   = (htid >> 5) & 1;        // warp half within q
    const int blockRow = blockIdx.x * ROWS_PER_CTA;
    const int R = blockRow + 14 * q;         // rows R..R+13

    // ---- stage weights (transposed, gate-packed) ----
    for (int idx = tid; idx < 76 * 64; idx += NTHREADS) {
        int k = idx >> 6, uu = idx & 63;
        float4 w;
        if (k < 12) {
            w.x = W_ih[uu * 12 + k];
            w.y = W_ih[(64 + uu) * 12 + k];
            w.z = W_ih[(128 + uu) * 12 + k];
            w.w = W_ih[(192 + uu) * 12 + k];
        } else {
            int kk = k - 12;
            w.x = W_hh[uu * 64 + kk];
            w.y = W_hh[(64 + uu) * 64 + kk];
            w.z = W_hh[(128 + uu) * 64 + kk];
            w.w = W_hh[(192 + uu) * 64 + kk];
        }
        s->wpack[k][uu] = w;
    }
    for (int idx = tid; idx < 64 * 64; idx += NTHREADS) {
        int uu = idx >> 6, k = idx & 63;
        s->w1t[k][uu] = W1[idx];
    }
    // h0 = 0 in phase 0 (k = 12..75, all slots)
    for (int idx = tid; idx < 64 * 17; idx += NTHREADS)
        s->xbuf[0][12 * 17 + idx] = make_float4(0.f, 0.f, 0.f, 0.f);
    // ---- copy hist_x into out[:, :64, :] (guarded) ----
    for (int idx = tid; idx < ROWS_PER_CTA * 192; idx += NTHREADS) {
        int rl = idx / 192, j = idx % 192;
        int grow = blockRow + rl;
        if (grow < BB)
            out[(size_t)grow * OUTSTR + j] = hist[(size_t)grow * 192 + j];
    }

    const float bi = b_ih[u] + b_hh[u];
    const float bf = b_ih[64 + u] + b_hh[64 + u];
    const float bg = b_ih[128 + u] + b_hh[128 + u];
    const float bo = b_ih[192 + u] + b_hh[192 + u];
    const float b1v = b1[u];
    const float w2v = W2[u];
    const float b2v = b2[0];

    float2 c7[NP], h7[NP], dist7[NP], pfv[NP];
#pragma unroll
    for (int p = 0; p < NP; ++p) {
        c7[p] = make_float2(0.f, 0.f);
        dist7[p] = make_float2(0.f, 0.f);
        pfv[p] = make_float2(0.f, 0.f);
    }
    // clamped row indices for this thread's pairs (only last CTA ever clamps)
    int rA[NP], rB[NP];
#pragma unroll
    for (int p = 0; p < NP; ++p) {
        rA[p] = min(R + 2 * p, BB - 1);
        rB[p] = min(R + 2 * p + 1, BB - 1);
    }

    // ---- prefetchers: only u<12 threads touch global memory ----
    auto pre_cond = [&](int j) {
        if (u < 4) {
            int ch = (u == 3) ? 2 : u;      // u==3 tracks ch2 for the dist cumsum
#pragma unroll
            for (int p = 0; p < NP; ++p) {
                pfv[p].x = hist[(size_t)rA[p] * 192 + j * 3 + ch];
                pfv[p].y = hist[(size_t)rB[p] * 192 + j * 3 + ch];
            }
        } else if (u < 12) {
            int ch = u - 4;
#pragma unroll
            for (int p = 0; p < NP; ++p) {
                pfv[p].x = noise[(size_t)rA[p] * 2048 + j * 8 + ch];
                pfv[p].y = noise[(size_t)rB[p] * 2048 + j * 8 + ch];
            }
        }
    };
    auto pre_gen = [&](int t) {
        if (u < 2) {
#pragma unroll
            for (int p = 0; p < NP; ++p) {
                pfv[p].x = gap[(size_t)rA[p] * 386 + t * 2 + u];
                pfv[p].y = gap[(size_t)rB[p] * 386 + t * 2 + u];
            }
        } else if (u >= 4 && u < 12) {
            if (t < 192) {
                int ch = u - 4;
#pragma unroll
                for (int p = 0; p < NP; ++p) {
                    pfv[p].x = noise[(size_t)rA[p] * 2048 + (64 + t) * 8 + ch];
                    pfv[p].y = noise[(size_t)rB[p] * 2048 + (64 + t) * 8 + ch];
                }
            } else {
#pragma unroll
                for (int p = 0; p < NP; ++p) pfv[p] = make_float2(0.f, 0.f);
            }
        }
    };
    auto write_x7 = [&](int ph, int k, const float2 v[NP]) {
        float4* dst = &s->xbuf[ph][k * 17 + q * 4];
        dst[0] = make_float4(v[0].x, v[0].y, v[1].x, v[1].y);
        dst[1] = make_float4(v[2].x, v[2].y, v[3].x, v[3].y);
        dst[2] = make_float4(v[4].x, v[4].y, v[5].x, v[5].y);
        *reinterpret_cast<float2*>(dst + 3) = v[6];
    };

    pre_cond(0);
    __syncthreads();   // staging + h0 visible (last full-CTA barrier)

    // ================= conditioning (64 steps, 1 half-barrier each) =================
    for (int j = 0; j < 64; ++j) {
        int ph = j & 1;
        if (u == 3) {                     // dist = inclusive cumsum of hist ch2
#pragma unroll
            for (int p = 0; p < NP; ++p) {
                dist7[p].x += pfv[p].x;
                dist7[p].y += pfv[p].y;
            }
            write_x7(ph, 3, dist7);
        } else if (u < 12) {
            write_x7(ph, u, pfv);
        }
        bar_half(half);                   // inputs + previous h visible (own half)
        if (j < 63) pre_cond(j + 1); else pre_gen(0);
        lstm_cond7(s, u, q, ph, bi, bf, bg, bo, c7, h7);
        write_x7(ph ^ 1, 12 + u, h7);
    }
    // write gen t=0 inputs into phase 0 (pfv holds pre_gen(0))
    if (u < 2 || (u >= 4 && u < 12)) write_x7(0, u, pfv);
    bar_half(half);   // h (phase 0), dist (phase 1), t=0 inputs visible

    // all threads pick up final dist from phase 1, k=3 (own q)
    {
        const float4* src = &s->xbuf[1][3 * 17 + q * 4];
        float4 v0 = src[0], v1 = src[1], v2 = src[2];
        float2 v3 = *reinterpret_cast<const float2*>(src + 3);
        dist7[0] = make_float2(v0.x, v0.y);
        dist7[1] = make_float2(v0.z, v0.w);
        dist7[2] = make_float2(v1.x, v1.y);
        dist7[3] = make_float2(v1.z, v1.w);
        dist7[4] = make_float2(v2.x, v2.y);
        dist7[5] = make_float2(v2.z, v2.w);
        dist7[6] = v3;
    }

    // ================= generation (192 full steps + MLP epilogue) =================
    for (int t = 0; t < 192; ++t) {
        int ph = t & 1;
        int trow = (64 + t) * 3;
        // gap outputs for step t (pfv holds step-t values)
        if (u < 2) {
#pragma unroll
            for (int p = 0; p < NP; ++p) {
                if (R + 2 * p < BB)     out[(size_t)(R + 2 * p) * OUTSTR + trow + u] = pfv[p].x;
                if (R + 2 * p + 1 < BB) out[(size_t)(R + 2 * p + 1) * OUTSTR + trow + u] = pfv[p].y;
            }
        }
        pre_gen(t + 1);                   // pfv now holds step t+1 inputs

        // accumulators: gates + MLP
        float2 ai[NP], af7[NP], ag[NP], ao[NP], az[NP];
#pragma unroll
        for (int p = 0; p < NP; ++p) {
            ai[p] = make_float2(bi, bi);
            af7[p] = make_float2(bf, bf);
            ag[p] = make_float2(bg, bg);
            ao[p] = make_float2(bo, bo);
            az[p] = make_float2(b1v, b1v);
        }

        // ---- fused h loop: gates (k=12..75) + MLP, pipelined ----
        {
            const float4* wp  = &s->wpack[12][u];
            const float*  w1p = &s->w1t[0][u];
            const float4* xp  = &s->xbuf[ph][12 * 17 + q * 4];
            auto ldx3 = [&](int kh) { return *reinterpret_cast<const float2*>(xp + kh * 17 + 3); };
            float4 wc = wp[0];
            float  w1c = w1p[0];
            float4 a0 = xp[0], a1 = xp[1], a2 = xp[2];
            float2 a3 = ldx3(0);
#pragma unroll 4
            for (int kh = 0; kh < 63; ++kh) {
                float4 wn = wp[(kh + 1) * 64];
                float  w1n = w1p[(kh + 1) * 64];
                float4 n0 = xp[(kh + 1) * 17], n1 = xp[(kh + 1) * 17 + 1], n2 = xp[(kh + 1) * 17 + 2];
                float2 n3 = ldx3(kh + 1);
                float2 p0 = make_float2(a0.x, a0.y), p1 = make_float2(a0.z, a0.w);
                float2 p2 = make_float2(a1.x, a1.y), p3 = make_float2(a1.z, a1.w);
                float2 p4 = make_float2(a2.x, a2.y), p5 = make_float2(a2.z, a2.w);
                DO_GATES7(wc, p0, p1, p2, p3, p4, p5, a3, ai, af7, ag, ao);
                gate4(w1c, p0, p1, p2, p3, az[0], az[1], az[2], az[3]);
                gate3(w1c, p4, p5, a3, az[4], az[5], az[6]);
                wc = wn; w1c = w1n; a0 = n0; a1 = n1; a2 = n2; a3 = n3;
            }
            float2 p0 = make_float2(a0.x, a0.y), p1 = make_float2(a0.z, a0.w);
            float2 p2 = make_float2(a1.x, a1.y), p3 = make_float2(a1.z, a1.w);
            float2 p4 = make_float2(a2.x, a2.y), p5 = make_float2(a2.z, a2.w);
            DO_GATES7(wc, p0, p1, p2, p3, p4, p5, a3, ai, af7, ag, ao);
            gate4(w1c, p0, p1, p2, p3, az[0], az[1], az[2], az[3]);
            gate3(w1c, p4, p5, a3, az[4], az[5], az[6]);
        }
        // ---- input ks: 0,1,4..11 (from xbuf, written at end of prev step) ----
        {
            const float4* xp = &s->xbuf[ph][q * 4];
            const float4* wp = &s->wpack[0][u];
            auto doKx = [&](int k) {
                float4 wk = wp[k * 64];
                float4 X0 = xp[k * 17], X1 = xp[k * 17 + 1], X2 = xp[k * 17 + 2];
                float2 X3 = *reinterpret_cast<const float2*>(xp + k * 17 + 3);
                float2 p0 = make_float2(X0.x, X0.y), p1 = make_float2(X0.z, X0.w);
                float2 p2 = make_float2(X1.x, X1.y), p3 = make_float2(X1.z, X1.w);
                float2 p4 = make_float2(X2.x, X2.y), p5 = make_float2(X2.z, X2.w);
                DO_GATES7(wk, p0, p1, p2, p3, p4, p5, X3, ai, af7, ag, ao);
            };
            doKx(0); doKx(1);
#pragma unroll
            for (int k = 4; k < 12; ++k) doKx(k);
        }
        // ---- z partials + warp reduce + cross-warp exchange ----
        float2 part[NP];
#pragma unroll
        for (int p = 0; p < NP; ++p)
            part[p] = make_float2(tanha(az[p].x) * w2v, tanha(az[p].y) * w2v);
#pragma unroll
        for (int p = 0; p < NP; ++p) {
#pragma unroll
            for (int m = 16; m >= 1; m >>= 1) {
                part[p].x += __shfl_xor_sync(0xffffffffu, part[p].x, m);
                part[p].y += __shfl_xor_sync(0xffffffffu, part[p].y, m);
            }
        }
        if (lane == 0) {
#pragma unroll
            for (int p = 0; p < NP; ++p) s->zhalf[q][wh][p] = part[p];
        }
        bar_half(half);                   // zhalf visible (own half)

        // ---- dp / dist, finish gates (k=2,3), nonlinearities ----
        float2 dp[NP];
#pragma unroll
        for (int p = 0; p < NP; ++p) {
            float2 za = s->zhalf[q][0][p];
            float2 zb = s->zhalf[q][1][p];
            dp[p].x = 24.f * tanha(za.x + zb.x + b2v);
            dp[p].y = 24.f * tanha(za.y + zb.y + b2v);
            dist7[p].x += dp[p].x;
            dist7[p].y += dp[p].y;
        }
        {
            float4 w2p = s->wpack[2][u];
            float4 w3p = s->wpack[3][u];
            DO_GATES7(w2p, dp[0], dp[1], dp[2], dp[3], dp[4], dp[5], dp[6], ai, af7, ag, ao);
            DO_GATES7(w3p, dist7[0], dist7[1], dist7[2], dist7[3], dist7[4], dist7[5], dist7[6],
                      ai, af7, ag, ao);
        }
#pragma unroll
        for (int p = 0; p < NP; ++p) {
            float ix = siga(ai[p].x), fx = siga(af7[p].x), gx = tanha(ag[p].x), ox = siga(ao[p].x);
            c7[p].x = fmaf(fx, c7[p].x, ix * gx);
            h7[p].x = ox * tanha(c7[p].x);
            float iy = siga(ai[p].y), fy = siga(af7[p].y), gy = tanha(ag[p].y), oy = siga(ao[p].y);
            c7[p].y = fmaf(fy, c7[p].y, iy * gy);
            h7[p].y = oy * tanha(c7[p].y);
        }
        // dp outputs
        if (u == 2) {
#pragma unroll
            for (int p = 0; p < NP; ++p) {
                if (R + 2 * p < BB)     out[(size_t)(R + 2 * p) * OUTSTR + trow + 2] = dp[p].x;
                if (R + 2 * p + 1 < BB) out[(size_t)(R + 2 * p + 1) * OUTSTR + trow + 2] = dp[p].y;
            }
        }
        // write h + step t+1 inputs into phase ph^1
        write_x7(ph ^ 1, 12 + u, h7);
        if (u < 2 || (u >= 4 && u < 12)) write_x7(ph ^ 1, u, pfv);
        bar_half(half);                   // visible for next step (own half)
    }

    // ---- epilogue t=192: outputs only (gap + dp from MLP on final h) ----
    {
        const int ph = 0;                 // 192 & 1
        const int trow = (64 + 192) * 3;
        if (u < 2) {
#pragma unroll
            for (int p = 0; p < NP; ++p) {
                if (R + 2 * p < BB)     out[(size_t)(R + 2 * p) * OUTSTR + trow + u] = pfv[p].x;
                if (R + 2 * p + 1 < BB) out[(size_t)(R + 2 * p + 1) * OUTSTR + trow + u] = pfv[p].y;
            }
        }
        float2 az[NP];
#pragma unroll
        for (int p = 0; p < NP; ++p) az[p] = make_float2(b1v, b1v);
        {
            const float*  w1p = &s->w1t[0][u];
            const float4* xp  = &s->xbuf[ph][12 * 17 + q * 4];
#pragma unroll 4
            for (int k = 0; k < 64; ++k) {
                float wv = w1p[k * 64];
                float4 X0 = xp[k * 17], X1 = xp[k * 17 + 1], X2 = xp[k * 17 + 2];
                float2 X3 = *reinterpret_cast<const float2*>(xp + k * 17 + 3);
                gate4(wv, make_float2(X0.x, X0.y), make_float2(X0.z, X0.w),
                      make_float2(X1.x, X1.y), make_float2(X1.z, X1.w),
                      az[0], az[1], az[2], az[3]);
                gate3(wv, make_float2(X2.x, X2.y), make_float2(X2.z, X2.w), X3,
                      az[4], az[5], az[6]);
            }
        }
        float2 part[NP];
#pragma unroll
        for (int p = 0; p < NP; ++p)
            part[p] = make_float2(tanha(az[p].x) * w2v, tanha(az[p].y) * w2v);
#pragma unroll
        for (int p = 0; p < NP; ++p) {
#pragma unroll
            for (int m = 16; m >= 1; m >>= 1) {
                part[p].x += __shfl_xor_sync(0xffffffffu, part[p].x, m);
                part[p].y += __shfl_xor_sync(0xffffffffu, part[p].y, m);
            }
        }
        if (lane == 0) {
#pragma unroll
            for (int p = 0; p < NP; ++p) s->zhalf[q][wh][p] = part[p];
        }
        bar_half(half);
        if (u == 2) {
#pragma unroll
            for (int p = 0; p < NP; ++p) {
                float2 za = s->zhalf[q][0][p];
                float2 zb = s->zhalf[q][1][p];
                float dx = 24.f * tanha(za.x + zb.x + b2v);
                float dy = 24.f * tanha(za.y + zb.y + b2v);
                if (R + 2 * p < BB)     out[(size_t)(R + 2 * p) * OUTSTR + trow + 2] = dx;
                if (R + 2 * p + 1 < BB) out[(size_t)(R + 2 * p + 1) * OUTSTR + trow + 2] = dy;
            }
        }
    }
}

extern "C" void kernel_launch(void* const* d_in, const int* in_sizes, int n_in,
                              void* d_out, int out_size) {
    const float* noise = (const float*)d_in[0];
    const float* hist  = (const float*)d_in[1];
    const float* gap   = (const float*)d_in[2];
    const float* W_ih  = (const float*)d_in[3];
    const float* W_hh  = (const float*)d_in[4];
    const float* b_ih  = (const float*)d_in[5];
    const float* b_hh  = (const float*)d_in[6];
    const float* W1    = (const float*)d_in[7];
    const float* b1    = (const float*)d_in[8];
    const float* W2    = (const float*)d_in[9];
    const float* b2    = (const float*)d_in[10];
    float* out = (float*)d_out;

    size_t smem = sizeof(SMem);
    cudaFuncSetAttribute(lstm_fused, cudaFuncAttributeMaxDynamicSharedMemorySize, (int)smem);
    lstm_fused<<<NCTA, NTHREADS, smem>>>(noise, hist, gap, W_ih, W_hh, b_ih, b_hh,
                                         W1, b1, W2, b2, out);
}